// round 14
// baseline (speedup 1.0000x reference)
#include <cuda_runtime.h>
#include <cstdint>

#define T_STEPS 512
#define BATCH   32
#define HID     512
#define G4      2048
#define STRIDE  516
#define PSTR    20
#define SECT    ((size_t)2 * T_STEPS * BATCH * HID)

// ---------------- device scratch ----------------
__device__ __align__(16) float g_pre[(size_t)T_STEPS * BATCH * G4];    // layer-0 pre-projection (tf32 GEMM)
__device__ __align__(16) float g_pre1h[(size_t)T_STEPS * BATCH * G4];  // pre1half: Wih1[:,0:256] @ h0 (fp32)
__device__ __align__(16) float g_h1[2][BATCH * HID];                   // h1 ring
__device__ unsigned g_bar0, g_bar1;

__global__ void reset_bar() { g_bar0 = 0u; g_bar1 = 0u; }

// ================= pre-projection GEMM (layer 0 only): tf32 tensor cores =================
#define KSTR 136

__device__ __forceinline__ unsigned f2tf32(float f) {
    unsigned u;
    asm("cvt.rna.tf32.f32 %0, %1;" : "=r"(u) : "f"(f));
    return u;
}

__device__ __forceinline__ void mma_tf32(float c[4], const unsigned a[4],
                                         unsigned b0, unsigned b1) {
    asm volatile(
        "mma.sync.aligned.m16n8k8.row.col.f32.tf32.tf32.f32 "
        "{%0,%1,%2,%3}, {%4,%5,%6,%7}, {%8,%9}, {%0,%1,%2,%3};"
        : "+f"(c[0]), "+f"(c[1]), "+f"(c[2]), "+f"(c[3])
        : "r"(a[0]), "r"(a[1]), "r"(a[2]), "r"(a[3]), "r"(b0), "r"(b1));
}

__global__ void __launch_bounds__(256) pre_gemm_tc(
    const float* __restrict__ A, const float* __restrict__ W,
    const float* __restrict__ bih, const float* __restrict__ bhh)
{
    __shared__ unsigned As[2][16 * KSTR];
    __shared__ unsigned Ws[2][16 * KSTR];

    const int tid  = threadIdx.x;
    const int brow = blockIdx.x * 128;
    const int bcol = blockIdx.y * 128;
    const int lane = tid & 31, wid = tid >> 5;
    const int grp  = lane >> 2, tg = lane & 3;
    const int m0w  = (wid & 3) * 32;
    const int n0w  = (wid >> 2) * 64;

    const int sr0 = tid >> 2,         sk0 = (tid & 3) << 2;
    const int sr1 = (tid + 256) >> 2, sk1 = sk0;

    float c[2][8][4];
#pragma unroll
    for (int mt = 0; mt < 2; mt++)
#pragma unroll
        for (int nt = 0; nt < 8; nt++)
#pragma unroll
            for (int i = 0; i < 4; i++) c[mt][nt][i] = 0.f;

    const float* Ap = A + (size_t)brow * HID;
    const float* Wp = W + (size_t)bcol * HID;

    {
        float4 a0 = *(const float4*)(Ap + (size_t)sr0 * HID + sk0);
        float4 a1 = *(const float4*)(Ap + (size_t)sr1 * HID + sk1);
        float4 w0 = *(const float4*)(Wp + (size_t)sr0 * HID + sk0);
        float4 w1 = *(const float4*)(Wp + (size_t)sr1 * HID + sk1);
        As[0][(sk0 + 0) * KSTR + sr0] = f2tf32(a0.x);
        As[0][(sk0 + 1) * KSTR + sr0] = f2tf32(a0.y);
        As[0][(sk0 + 2) * KSTR + sr0] = f2tf32(a0.z);
        As[0][(sk0 + 3) * KSTR + sr0] = f2tf32(a0.w);
        As[0][(sk1 + 0) * KSTR + sr1] = f2tf32(a1.x);
        As[0][(sk1 + 1) * KSTR + sr1] = f2tf32(a1.y);
        As[0][(sk1 + 2) * KSTR + sr1] = f2tf32(a1.z);
        As[0][(sk1 + 3) * KSTR + sr1] = f2tf32(a1.w);
        Ws[0][(sk0 + 0) * KSTR + sr0] = f2tf32(w0.x);
        Ws[0][(sk0 + 1) * KSTR + sr0] = f2tf32(w0.y);
        Ws[0][(sk0 + 2) * KSTR + sr0] = f2tf32(w0.z);
        Ws[0][(sk0 + 3) * KSTR + sr0] = f2tf32(w0.w);
        Ws[0][(sk1 + 0) * KSTR + sr1] = f2tf32(w1.x);
        Ws[0][(sk1 + 1) * KSTR + sr1] = f2tf32(w1.y);
        Ws[0][(sk1 + 2) * KSTR + sr1] = f2tf32(w1.z);
        Ws[0][(sk1 + 3) * KSTR + sr1] = f2tf32(w1.w);
    }

    int buf = 0;
    for (int kt = 0; kt < 32; kt++) {
        const bool nxt = (kt + 1) < 32;
        float4 na0, na1, nw0, nw1;
        if (nxt) {
            const int k0 = (kt + 1) * 16;
            na0 = *(const float4*)(Ap + (size_t)sr0 * HID + k0 + sk0);
            na1 = *(const float4*)(Ap + (size_t)sr1 * HID + k0 + sk1);
            nw0 = *(const float4*)(Wp + (size_t)sr0 * HID + k0 + sk0);
            nw1 = *(const float4*)(Wp + (size_t)sr1 * HID + k0 + sk1);
        }
        __syncthreads();

        const unsigned* Asb = As[buf];
        const unsigned* Wsb = Ws[buf];
#pragma unroll
        for (int k8 = 0; k8 < 16; k8 += 8) {
            unsigned af[2][4];
#pragma unroll
            for (int mt = 0; mt < 2; mt++) {
                const int m = m0w + mt * 16 + grp;
                af[mt][0] = Asb[(k8 + tg) * KSTR + m];
                af[mt][1] = Asb[(k8 + tg) * KSTR + m + 8];
                af[mt][2] = Asb[(k8 + tg + 4) * KSTR + m];
                af[mt][3] = Asb[(k8 + tg + 4) * KSTR + m + 8];
            }
#pragma unroll
            for (int nt = 0; nt < 8; nt++) {
                const int n = n0w + nt * 8 + grp;
                unsigned b0 = Wsb[(k8 + tg) * KSTR + n];
                unsigned b1 = Wsb[(k8 + tg + 4) * KSTR + n];
                mma_tf32(c[0][nt], af[0], b0, b1);
                mma_tf32(c[1][nt], af[1], b0, b1);
            }
        }

        if (nxt) {
            __syncthreads();
            const int nb = buf ^ 1;
            As[nb][(sk0 + 0) * KSTR + sr0] = f2tf32(na0.x);
            As[nb][(sk0 + 1) * KSTR + sr0] = f2tf32(na0.y);
            As[nb][(sk0 + 2) * KSTR + sr0] = f2tf32(na0.z);
            As[nb][(sk0 + 3) * KSTR + sr0] = f2tf32(na0.w);
            As[nb][(sk1 + 0) * KSTR + sr1] = f2tf32(na1.x);
            As[nb][(sk1 + 1) * KSTR + sr1] = f2tf32(na1.y);
            As[nb][(sk1 + 2) * KSTR + sr1] = f2tf32(na1.z);
            As[nb][(sk1 + 3) * KSTR + sr1] = f2tf32(na1.w);
            Ws[nb][(sk0 + 0) * KSTR + sr0] = f2tf32(nw0.x);
            Ws[nb][(sk0 + 1) * KSTR + sr0] = f2tf32(nw0.y);
            Ws[nb][(sk0 + 2) * KSTR + sr0] = f2tf32(nw0.z);
            Ws[nb][(sk0 + 3) * KSTR + sr0] = f2tf32(nw0.w);
            Ws[nb][(sk1 + 0) * KSTR + sr1] = f2tf32(nw1.x);
            Ws[nb][(sk1 + 1) * KSTR + sr1] = f2tf32(nw1.y);
            Ws[nb][(sk1 + 2) * KSTR + sr1] = f2tf32(nw1.z);
            Ws[nb][(sk1 + 3) * KSTR + sr1] = f2tf32(nw1.w);
        }
        buf ^= 1;
    }

#pragma unroll
    for (int nt = 0; nt < 8; nt++) {
        const int colg = bcol + n0w + nt * 8 + 2 * tg;
        const float bb0 = bih[colg] + bhh[colg];
        const float bb1 = bih[colg + 1] + bhh[colg + 1];
#pragma unroll
        for (int mt = 0; mt < 2; mt++) {
            const int row = brow + m0w + mt * 16 + grp;
            float2 o0 = make_float2(c[mt][nt][0] + bb0, c[mt][nt][1] + bb1);
            float2 o1 = make_float2(c[mt][nt][2] + bb0, c[mt][nt][3] + bb1);
            *(float2*)&g_pre[(size_t)row * G4 + colg]       = o0;
            *(float2*)&g_pre[(size_t)(row + 8) * G4 + colg] = o1;
        }
    }
}

// ================= dual-group persistent recurrence =================
#define FMA2(d, a, b) \
    asm("fma.rn.f32x2 %0, %1, %2, %0;" : "+l"(d) : "l"(a), "l"(b))

// one 32-k chunk: w from global (8 x ulonglong2), h from smem, 16 batches
__device__ __forceinline__ void mv_chunk(const float* __restrict__ hp,
                                         const float* __restrict__ wp,
                                         unsigned long long acc2[16])
{
    ulonglong2 wq[8];
#pragma unroll
    for (int q = 0; q < 8; q++)
        wq[q] = *(const ulonglong2*)__builtin_assume_aligned(wp + q * 4, 16);
#pragma unroll
    for (int q = 0; q < 8; q++) {
        const unsigned long long wlo = wq[q].x, whi = wq[q].y;
#pragma unroll
        for (int b = 0; b < 16; b++) {
            ulonglong2 h2 = *(const ulonglong2*)(hp + (size_t)b * STRIDE + q * 4);
            FMA2(acc2[b], h2.x, wlo);
            FMA2(acc2[b], h2.y, whi);
        }
    }
}

__device__ __forceinline__ void store_part(const unsigned long long acc2[16],
                                           float* __restrict__ pr)
{
#pragma unroll
    for (int b4 = 0; b4 < 4; b4++) {
        float4 v;
        v.x = __uint_as_float((unsigned)acc2[b4 * 4 + 0]) + __uint_as_float((unsigned)(acc2[b4 * 4 + 0] >> 32));
        v.y = __uint_as_float((unsigned)acc2[b4 * 4 + 1]) + __uint_as_float((unsigned)(acc2[b4 * 4 + 1] >> 32));
        v.z = __uint_as_float((unsigned)acc2[b4 * 4 + 2]) + __uint_as_float((unsigned)(acc2[b4 * 4 + 2] >> 32));
        v.w = __uint_as_float((unsigned)acc2[b4 * 4 + 3]) + __uint_as_float((unsigned)(acc2[b4 * 4 + 3] >> 32));
        *(float4*)(pr + b4 * 4) = v;
    }
}

__device__ __forceinline__ void spin_ge(unsigned* bar, unsigned target) {
    unsigned v;
    do {
        asm volatile("ld.acquire.gpu.global.u32 %0, [%1];" : "=r"(v) : "l"(bar) : "memory");
    } while (v < target);
}

__global__ void __launch_bounds__(512, 1) lstm_dual(
    const float* __restrict__ whh0, const float* __restrict__ wih1,
    const float* __restrict__ whh1,
    const float* __restrict__ bih1, const float* __restrict__ bhh1,
    float* __restrict__ out)
{
    extern __shared__ float sm[];
    float* h0_s  = sm;                    // [32][STRIDE]
    float* h1_s  = sm + 32 * STRIDE;      // [32][STRIDE]  (L1 only; L0 uses region as part2)
    float* part  = sm + 64 * STRIDE;      // [512][PSTR]
    float* part2 = h1_s;                  // L0 overlay: [512][PSTR] fits in 66KB region

    const int tid  = threadIdx.x;
    const int col  = tid & 31;            // gate*8 + jj
    const int ksub = (tid >> 5) & 7;
    const int bh   = tid >> 8;
    const int gate = col >> 3, jj = col & 7;

    // epilogue mapping (both groups): tid<256 -> (b, jj) cell; tid in [256,512) -> pre1half cell (L0)
    const int ajj = (tid & 255) >> 5;
    const int ab  = tid & 31;
    const int bhi = ab >> 4, bl = ab & 15;

    float* prth = part + (size_t)(((ksub * 2 + bh) * 32 + col) * PSTR);
    const float* hp0 = h0_s + (size_t)(bh * 16) * STRIDE;
    const float* hp1 = h1_s + (size_t)(bh * 16) * STRIDE;

    if (blockIdx.x < 64) {
        // ================= LAYER 0 GROUP =================
        const int jblk = blockIdx.x;
        const int jglob = jblk * 8;
        const int wrow = gate * HID + jglob + jj;
        const float* w0p = whh0 + (size_t)wrow * HID;
        const float* w1p = wih1 + (size_t)wrow * HID;
        float* pr2th = part2 + (size_t)(((ksub * 2 + bh) * 32 + col) * PSTR);
        float c0 = 0.f;

        for (int t = 0; t <= T_STEPS; t++) {
            // prefetch layer-0 pre-projection for step t
            float pre0g[4];
            if (tid < 256 && t < T_STEPS) {
                const float* pp = g_pre + ((size_t)t * BATCH + ab) * G4 + jglob + ajj;
#pragma unroll
                for (int g = 0; g < 4; g++) pre0g[g] = __ldg(pp + g * HID);
            }

            // stage h0[t-1]
            if (t == 0) {
#pragma unroll
                for (int q = 0; q < 8; q++) {
                    int lin = q * 512 + tid;
                    int b = lin >> 7, kq = (lin & 127) << 2;
                    *(float4*)&h0_s[b * STRIDE + kq] = make_float4(0.f, 0.f, 0.f, 0.f);
                }
            } else {
                const float* hb = out + ((size_t)(t - 1) * BATCH) * HID;
#pragma unroll
                for (int q = 0; q < 8; q++) {
                    int lin = q * 512 + tid;
                    int b = lin >> 7, kq = (lin & 127) << 2;
                    *(float4*)&h0_s[b * STRIDE + kq] = __ldcg((const float4*)(hb + (size_t)b * HID + kq));
                }
            }
            __syncthreads();

            // pass A: own gates (k=512, chunks at ksub*64 + {0,32})
            {
                unsigned long long acc2[16];
#pragma unroll
                for (int b = 0; b < 16; b++) acc2[b] = 0ull;
                mv_chunk(hp0 + ksub * 64,      w0p + ksub * 64,      acc2);
                mv_chunk(hp0 + ksub * 64 + 32, w0p + ksub * 64 + 32, acc2);
                store_part(acc2, prth);
            }
            // pass B: pre1half = Wih1[:,0:256] @ h0[t-1]  (k=256, chunk at ksub*32)
            {
                unsigned long long acc2[16];
#pragma unroll
                for (int b = 0; b < 16; b++) acc2[b] = 0ull;
                mv_chunk(hp0 + ksub * 32, w1p + ksub * 32, acc2);
                store_part(acc2, pr2th);
            }
            __syncthreads();

            // epilogue 1 (tid<256): layer-0 cell update for (ab, jglob+ajj)
            if (tid < 256 && t < T_STEPS) {
                float gs[4];
#pragma unroll
                for (int g = 0; g < 4; g++) {
                    int c = g * 8 + ajj;
                    float s = pre0g[g];
#pragma unroll
                    for (int ks = 0; ks < 8; ks++)
                        s += part[((ks * 2 + bhi) * 32 + c) * PSTR + bl];
                    gs[g] = s;
                }
                float i_t = 1.f / (1.f + __expf(-gs[0]));
                float f_t = 1.f / (1.f + __expf(-gs[1]));
                float g_t = __fdividef(2.f, 1.f + __expf(-2.f * gs[2])) - 1.f;
                float o_t = 1.f / (1.f + __expf(-gs[3]));
                float c_new = f_t * c0 + i_t * g_t;
                float tc    = __fdividef(2.f, 1.f + __expf(-2.f * c_new)) - 1.f;
                float h_new = o_t * tc;
                c0 = c_new;
                size_t oidx = ((size_t)t * BATCH + ab) * HID + jglob + ajj;
                out[oidx]            = h_new;
                out[SECT + oidx]     = c_new;
                out[2 * SECT + oidx] = i_t;
                out[3 * SECT + oidx] = f_t;
                out[4 * SECT + oidx] = g_t;
                out[5 * SECT + oidx] = o_t;
            }
            // epilogue 2 (tid>=256): store pre1half[t-1]
            if (tid >= 256 && t >= 1) {
                size_t base = ((size_t)(t - 1) * BATCH + ab) * G4 + jglob + ajj;
#pragma unroll
                for (int g = 0; g < 4; g++) {
                    int c = g * 8 + ajj;
                    float s = 0.f;
#pragma unroll
                    for (int ks = 0; ks < 8; ks++)
                        s += part2[((ks * 2 + bhi) * 32 + c) * PSTR + bl];
                    g_pre1h[base + g * HID] = s;
                }
            }
            __syncthreads();
            if (tid == 0) {
                asm volatile("red.release.gpu.global.add.u32 [%0], 1;" :: "l"(&g_bar0) : "memory");
                spin_ge(&g_bar0, (unsigned)(t + 1) * 64u);
            }
            __syncthreads();
        }
    } else {
        // ================= LAYER 1 GROUP =================
        const int jblk = blockIdx.x - 64;
        const int jglob = jblk * 8;
        const int wrow = gate * HID + jglob + jj;
        const float* w1p  = wih1 + (size_t)wrow * HID;
        const float* w2p  = whh1 + (size_t)wrow * HID;
        float bias1g[4];
        if (tid < 256) {
#pragma unroll
            for (int g = 0; g < 4; g++) {
                int r = g * HID + jglob + ajj;
                bias1g[g] = bih1[r] + bhh1[r];
            }
        }
        float c1 = 0.f;

        for (int t = 0; t < T_STEPS; t++) {
            // wait: L0 must have finished step t+1 (h0[t] + pre1half[t] published)
            if (tid == 0) spin_ge(&g_bar0, (unsigned)(t + 2) * 64u);
            __syncthreads();

            // prefetch pre1half[t]
            float ph1[4];
            if (tid < 256) {
                const float* pp = g_pre1h + ((size_t)t * BATCH + ab) * G4 + jglob + ajj;
#pragma unroll
                for (int g = 0; g < 4; g++) ph1[g] = __ldcg(pp + g * HID);
            }

            // stage h0[t] upper half (k 256..511) from out
            {
                const float* hb = out + ((size_t)t * BATCH) * HID;
#pragma unroll
                for (int q = 0; q < 4; q++) {
                    int lin = q * 512 + tid;
                    int b = lin >> 6, kq = 256 + ((lin & 63) << 2);
                    *(float4*)&h0_s[b * STRIDE + kq] = __ldcg((const float4*)(hb + (size_t)b * HID + kq));
                }
            }
            // stage h1[t-1]
            if (t == 0) {
#pragma unroll
                for (int q = 0; q < 8; q++) {
                    int lin = q * 512 + tid;
                    int b = lin >> 7, kq = (lin & 127) << 2;
                    *(float4*)&h1_s[b * STRIDE + kq] = make_float4(0.f, 0.f, 0.f, 0.f);
                }
            } else {
                const float* hb = g_h1[t & 1];
#pragma unroll
                for (int q = 0; q < 8; q++) {
                    int lin = q * 512 + tid;
                    int b = lin >> 7, kq = (lin & 127) << 2;
                    *(float4*)&h1_s[b * STRIDE + kq] = __ldcg((const float4*)(hb + (size_t)b * HID + kq));
                }
            }
            __syncthreads();

            // pass: k=768 concat [Wih1[:,256:512]@h0half | Whh1@h1], 3 chunks of 32
            {
                unsigned long long acc2[16];
#pragma unroll
                for (int b = 0; b < 16; b++) acc2[b] = 0ull;
#pragma unroll
                for (int ph = 0; ph < 3; ph++) {
                    const int koff = ksub * 96 + ph * 32;
                    if (koff < 256)
                        mv_chunk(hp0 + 256 + koff, w1p + 256 + koff, acc2);
                    else
                        mv_chunk(hp1 + (koff - 256), w2p + (koff - 256), acc2);
                }
                store_part(acc2, prth);
            }
            __syncthreads();

            // epilogue: layer-1 cell update
            if (tid < 256) {
                float gs[4];
#pragma unroll
                for (int g = 0; g < 4; g++) {
                    int c = g * 8 + ajj;
                    float s = bias1g[g] + ph1[g];
#pragma unroll
                    for (int ks = 0; ks < 8; ks++)
                        s += part[((ks * 2 + bhi) * 32 + c) * PSTR + bl];
                    gs[g] = s;
                }
                float i_t = 1.f / (1.f + __expf(-gs[0]));
                float f_t = 1.f / (1.f + __expf(-gs[1]));
                float g_t = __fdividef(2.f, 1.f + __expf(-2.f * gs[2])) - 1.f;
                float o_t = 1.f / (1.f + __expf(-gs[3]));
                float c_new = f_t * c1 + i_t * g_t;
                float tc    = __fdividef(2.f, 1.f + __expf(-2.f * c_new)) - 1.f;
                float h_new = o_t * tc;
                c1 = c_new;
                size_t oidx = ((size_t)(T_STEPS + t) * BATCH + ab) * HID + jglob + ajj;
                out[oidx]            = h_new;
                out[SECT + oidx]     = c_new;
                out[2 * SECT + oidx] = i_t;
                out[3 * SECT + oidx] = f_t;
                out[4 * SECT + oidx] = g_t;
                out[5 * SECT + oidx] = o_t;
                g_h1[(t + 1) & 1][ab * HID + jglob + ajj] = h_new;
            }
            __syncthreads();
            if (tid == 0) {
                asm volatile("red.release.gpu.global.add.u32 [%0], 1;" :: "l"(&g_bar1) : "memory");
                spin_ge(&g_bar1, (unsigned)(t + 1) * 64u);
            }
            __syncthreads();
        }
    }
}

// ---------------- launch ----------------
extern "C" void kernel_launch(void* const* d_in, const int* in_sizes, int n_in,
                              void* d_out, int out_size)
{
    (void)in_sizes; (void)n_in; (void)out_size;
    const float* x    = (const float*)d_in[0];
    const float* w_ih = (const float*)d_in[1];
    const float* w_hh = (const float*)d_in[2];
    const float* b_ih = (const float*)d_in[3];
    const float* b_hh = (const float*)d_in[4];
    float* out = (float*)d_out;

    const int smem = (64 * STRIDE + 512 * PSTR) * 4;  // 173056 B
    cudaFuncSetAttribute(lstm_dual, cudaFuncAttributeMaxDynamicSharedMemorySize, smem);

    dim3 gg(T_STEPS * BATCH / 128, G4 / 128);  // (128, 16)
    pre_gemm_tc<<<gg, 256>>>(x, w_ih, b_ih, b_hh);   // layer 0 only
    reset_bar<<<1, 1>>>();
    lstm_dual<<<128, 512, smem>>>(w_hh,
                                  w_ih + (size_t)G4 * HID,
                                  w_hh + (size_t)G4 * HID,
                                  b_ih + G4, b_hh + G4, out);
}

// round 15
// speedup vs baseline: 1.7744x; 1.7744x over previous
#include <cuda_runtime.h>
#include <cstdint>

#define T_STEPS 512
#define BATCH   32
#define HID     512
#define G4      2048
#define NBLK    128
#define NGRP    2
#define GBLK    64                 // blocks per group
#define BPG     16                 // batches per group
#define STRIDE  516
#define PSTR    20
#define SECT    ((size_t)2 * T_STEPS * BATCH * HID)

// ---------------- device scratch ----------------
__device__ __align__(16) float g_pre[(size_t)T_STEPS * BATCH * G4];
__device__ __align__(16) float g_hbuf[2][BATCH * HID];
__device__ unsigned g_barg[NGRP][32];    // one counter per group, 128B apart

__global__ void reset_bar() {
    if (threadIdx.x < NGRP) g_barg[threadIdx.x][0] = 0u;
}

// ================= pre-projection GEMM: tf32 tensor cores (unchanged from R6) ========
#define KSTR 136

__device__ __forceinline__ unsigned f2tf32(float f) {
    unsigned u;
    asm("cvt.rna.tf32.f32 %0, %1;" : "=r"(u) : "f"(f));
    return u;
}

__device__ __forceinline__ void mma_tf32(float c[4], const unsigned a[4],
                                         unsigned b0, unsigned b1) {
    asm volatile(
        "mma.sync.aligned.m16n8k8.row.col.f32.tf32.tf32.f32 "
        "{%0,%1,%2,%3}, {%4,%5,%6,%7}, {%8,%9}, {%0,%1,%2,%3};"
        : "+f"(c[0]), "+f"(c[1]), "+f"(c[2]), "+f"(c[3])
        : "r"(a[0]), "r"(a[1]), "r"(a[2]), "r"(a[3]), "r"(b0), "r"(b1));
}

__global__ void __launch_bounds__(256) pre_gemm_tc(
    const float* __restrict__ A, const float* __restrict__ W,
    const float* __restrict__ bih, const float* __restrict__ bhh)
{
    __shared__ unsigned As[2][16 * KSTR];
    __shared__ unsigned Ws[2][16 * KSTR];

    const int tid  = threadIdx.x;
    const int brow = blockIdx.x * 128;
    const int bcol = blockIdx.y * 128;
    const int lane = tid & 31, wid = tid >> 5;
    const int grp  = lane >> 2, tg = lane & 3;
    const int m0w  = (wid & 3) * 32;
    const int n0w  = (wid >> 2) * 64;

    const int sr0 = tid >> 2,         sk0 = (tid & 3) << 2;
    const int sr1 = (tid + 256) >> 2, sk1 = sk0;

    float c[2][8][4];
#pragma unroll
    for (int mt = 0; mt < 2; mt++)
#pragma unroll
        for (int nt = 0; nt < 8; nt++)
#pragma unroll
            for (int i = 0; i < 4; i++) c[mt][nt][i] = 0.f;

    const float* Ap = A + (size_t)brow * HID;
    const float* Wp = W + (size_t)bcol * HID;

    {
        float4 a0 = *(const float4*)(Ap + (size_t)sr0 * HID + sk0);
        float4 a1 = *(const float4*)(Ap + (size_t)sr1 * HID + sk1);
        float4 w0 = *(const float4*)(Wp + (size_t)sr0 * HID + sk0);
        float4 w1 = *(const float4*)(Wp + (size_t)sr1 * HID + sk1);
        As[0][(sk0 + 0) * KSTR + sr0] = f2tf32(a0.x);
        As[0][(sk0 + 1) * KSTR + sr0] = f2tf32(a0.y);
        As[0][(sk0 + 2) * KSTR + sr0] = f2tf32(a0.z);
        As[0][(sk0 + 3) * KSTR + sr0] = f2tf32(a0.w);
        As[0][(sk1 + 0) * KSTR + sr1] = f2tf32(a1.x);
        As[0][(sk1 + 1) * KSTR + sr1] = f2tf32(a1.y);
        As[0][(sk1 + 2) * KSTR + sr1] = f2tf32(a1.z);
        As[0][(sk1 + 3) * KSTR + sr1] = f2tf32(a1.w);
        Ws[0][(sk0 + 0) * KSTR + sr0] = f2tf32(w0.x);
        Ws[0][(sk0 + 1) * KSTR + sr0] = f2tf32(w0.y);
        Ws[0][(sk0 + 2) * KSTR + sr0] = f2tf32(w0.z);
        Ws[0][(sk0 + 3) * KSTR + sr0] = f2tf32(w0.w);
        Ws[0][(sk1 + 0) * KSTR + sr1] = f2tf32(w1.x);
        Ws[0][(sk1 + 1) * KSTR + sr1] = f2tf32(w1.y);
        Ws[0][(sk1 + 2) * KSTR + sr1] = f2tf32(w1.z);
        Ws[0][(sk1 + 3) * KSTR + sr1] = f2tf32(w1.w);
    }

    int buf = 0;
    for (int kt = 0; kt < 32; kt++) {
        const bool nxt = (kt + 1) < 32;
        float4 na0, na1, nw0, nw1;
        if (nxt) {
            const int k0 = (kt + 1) * 16;
            na0 = *(const float4*)(Ap + (size_t)sr0 * HID + k0 + sk0);
            na1 = *(const float4*)(Ap + (size_t)sr1 * HID + k0 + sk1);
            nw0 = *(const float4*)(Wp + (size_t)sr0 * HID + k0 + sk0);
            nw1 = *(const float4*)(Wp + (size_t)sr1 * HID + k0 + sk1);
        }
        __syncthreads();

        const unsigned* Asb = As[buf];
        const unsigned* Wsb = Ws[buf];
#pragma unroll
        for (int k8 = 0; k8 < 16; k8 += 8) {
            unsigned af[2][4];
#pragma unroll
            for (int mt = 0; mt < 2; mt++) {
                const int m = m0w + mt * 16 + grp;
                af[mt][0] = Asb[(k8 + tg) * KSTR + m];
                af[mt][1] = Asb[(k8 + tg) * KSTR + m + 8];
                af[mt][2] = Asb[(k8 + tg + 4) * KSTR + m];
                af[mt][3] = Asb[(k8 + tg + 4) * KSTR + m + 8];
            }
#pragma unroll
            for (int nt = 0; nt < 8; nt++) {
                const int n = n0w + nt * 8 + grp;
                unsigned b0 = Wsb[(k8 + tg) * KSTR + n];
                unsigned b1 = Wsb[(k8 + tg + 4) * KSTR + n];
                mma_tf32(c[0][nt], af[0], b0, b1);
                mma_tf32(c[1][nt], af[1], b0, b1);
            }
        }

        if (nxt) {
            __syncthreads();
            const int nb = buf ^ 1;
            As[nb][(sk0 + 0) * KSTR + sr0] = f2tf32(na0.x);
            As[nb][(sk0 + 1) * KSTR + sr0] = f2tf32(na0.y);
            As[nb][(sk0 + 2) * KSTR + sr0] = f2tf32(na0.z);
            As[nb][(sk0 + 3) * KSTR + sr0] = f2tf32(na0.w);
            As[nb][(sk1 + 0) * KSTR + sr1] = f2tf32(na1.x);
            As[nb][(sk1 + 1) * KSTR + sr1] = f2tf32(na1.y);
            As[nb][(sk1 + 2) * KSTR + sr1] = f2tf32(na1.z);
            As[nb][(sk1 + 3) * KSTR + sr1] = f2tf32(na1.w);
            Ws[nb][(sk0 + 0) * KSTR + sr0] = f2tf32(nw0.x);
            Ws[nb][(sk0 + 1) * KSTR + sr0] = f2tf32(nw0.y);
            Ws[nb][(sk0 + 2) * KSTR + sr0] = f2tf32(nw0.z);
            Ws[nb][(sk0 + 3) * KSTR + sr0] = f2tf32(nw0.w);
            Ws[nb][(sk1 + 0) * KSTR + sr1] = f2tf32(nw1.x);
            Ws[nb][(sk1 + 1) * KSTR + sr1] = f2tf32(nw1.y);
            Ws[nb][(sk1 + 2) * KSTR + sr1] = f2tf32(nw1.z);
            Ws[nb][(sk1 + 3) * KSTR + sr1] = f2tf32(nw1.w);
        }
        buf ^= 1;
    }

#pragma unroll
    for (int nt = 0; nt < 8; nt++) {
        const int colg = bcol + n0w + nt * 8 + 2 * tg;
        const float bb0 = bih[colg] + bhh[colg];
        const float bb1 = bih[colg + 1] + bhh[colg + 1];
#pragma unroll
        for (int mt = 0; mt < 2; mt++) {
            const int row = brow + m0w + mt * 16 + grp;
            float2 o0 = make_float2(c[mt][nt][0] + bb0, c[mt][nt][1] + bb1);
            float2 o1 = make_float2(c[mt][nt][2] + bb0, c[mt][nt][3] + bb1);
            *(float2*)&g_pre[(size_t)row * G4 + colg]       = o0;
            *(float2*)&g_pre[(size_t)(row + 8) * G4 + colg] = o1;
        }
    }
}

// ================= persistent recurrence: batch-split, 2 independent groups ===========
#define FMA2(d, a, b) \
    asm("fma.rn.f32x2 %0, %1, %2, %0;" : "+l"(d) : "l"(a), "l"(b))

__global__ void __launch_bounds__(512, 1) lstm_layer(
    int layer, const float* __restrict__ whh, float* __restrict__ out)
{
    extern __shared__ float sm[];
    float* h_s  = sm;                   // [BPG][STRIDE]  (16 rows)
    float* part = sm + BPG * STRIDE;    // [512][PSTR]

    const int tid  = threadIdx.x;
    const int col  = tid & 31;          // gate*8 + jj
    const int ksub = tid >> 5;          // 0..15
    const int grp  = blockIdx.x >> 6;   // 0/1: batch group
    const int jb   = blockIdx.x & 63;   // j-block: 8 hidden indices
    const int gate = col >> 3, jj = col & 7;

    // per-thread Whh chunk in registers (loaded once per layer)
    ulonglong2 wq[8];
    {
        const float* wp = whh + (size_t)(gate * HID + jb * 8 + jj) * HID + ksub * 32;
#pragma unroll
        for (int q = 0; q < 8; q++) wq[q] = *(const ulonglong2*)(wp + q * 4);
    }

    // epilogue threads (tid<128): one (batch, j) cell; ajj fastest -> 32B coalesced stores
    const int ajj   = tid & 7;
    const int ab    = (tid >> 3) & 15;
    const int bglob = grp * BPG + ab;
    const int aj    = jb * 8 + ajj;
    float c_state = 0.f;

    unsigned* bar = &g_barg[grp][0];
    float* prth = part + (size_t)((ksub * 32 + col) * PSTR);
    const float* hp = h_s + ksub * 32;

    for (int t = 0; t < T_STEPS; t++) {
        // ---- prefetch pre-projection for this step ----
        float preg[4];
        if (tid < 128) {
            const float* pp = g_pre + ((size_t)t * BATCH + bglob) * G4 + aj;
#pragma unroll
            for (int g = 0; g < 4; g++) preg[g] = __ldg(pp + g * HID);
        }

        // ---- stage this group's h_{t-1} (16 batches x 512) ----
        if (t == 0) {
#pragma unroll
            for (int q = 0; q < 4; q++) {
                int lin = q * 512 + tid;
                int b = lin >> 7, kq = (lin & 127) << 2;
                *(float4*)&h_s[b * STRIDE + kq] = make_float4(0.f, 0.f, 0.f, 0.f);
            }
        } else {
            const float* hb = g_hbuf[t & 1] + (size_t)grp * BPG * HID;
#pragma unroll
            for (int q = 0; q < 4; q++) {
                int lin = q * 512 + tid;
                int b = lin >> 7, kq = (lin & 127) << 2;
                *(float4*)&h_s[b * STRIDE + kq] = __ldcg((const float4*)(hb + (size_t)b * HID + kq));
            }
        }
        __syncthreads();

        // ---- partial dot-products: 256 FMA2 + 128 LDS.128 (full 32-lane broadcast) ----
        unsigned long long acc2[16];
#pragma unroll
        for (int b = 0; b < 16; b++) acc2[b] = 0ull;
#pragma unroll
        for (int q = 0; q < 8; q++) {
            const unsigned long long wlo = wq[q].x, whi = wq[q].y;
#pragma unroll
            for (int b = 0; b < 16; b++) {
                ulonglong2 h2 = *(const ulonglong2*)(hp + (size_t)b * STRIDE + q * 4);
                FMA2(acc2[b], h2.x, wlo);
                FMA2(acc2[b], h2.y, whi);
            }
        }
        // fold + write partials (80B rows, 16B-aligned STS.128, conflict-free)
#pragma unroll
        for (int b4 = 0; b4 < 4; b4++) {
            float4 v;
            v.x = __uint_as_float((unsigned)acc2[b4 * 4 + 0]) + __uint_as_float((unsigned)(acc2[b4 * 4 + 0] >> 32));
            v.y = __uint_as_float((unsigned)acc2[b4 * 4 + 1]) + __uint_as_float((unsigned)(acc2[b4 * 4 + 1] >> 32));
            v.z = __uint_as_float((unsigned)acc2[b4 * 4 + 2]) + __uint_as_float((unsigned)(acc2[b4 * 4 + 2] >> 32));
            v.w = __uint_as_float((unsigned)acc2[b4 * 4 + 3]) + __uint_as_float((unsigned)(acc2[b4 * 4 + 3] >> 32));
            *(float4*)(prth + b4 * 4) = v;
        }
        __syncthreads();

        // ---- reduce + activations + outputs ----
        if (tid < 128) {
            float gs[4];
#pragma unroll
            for (int g = 0; g < 4; g++) {
                int c = g * 8 + ajj;
                float s = preg[g];
#pragma unroll
                for (int ks = 0; ks < 16; ks++)
                    s += part[(ks * 32 + c) * PSTR + ab];
                gs[g] = s;
            }
            float i_t = 1.f / (1.f + __expf(-gs[0]));
            float f_t = 1.f / (1.f + __expf(-gs[1]));
            float g_t = __fdividef(2.f, 1.f + __expf(-2.f * gs[2])) - 1.f;
            float o_t = 1.f / (1.f + __expf(-gs[3]));
            float c_new = f_t * c_state + i_t * g_t;
            float tc    = __fdividef(2.f, 1.f + __expf(-2.f * c_new)) - 1.f;
            float h_new = o_t * tc;
            c_state = c_new;
            g_hbuf[(t + 1) & 1][(size_t)bglob * HID + aj] = h_new;
            size_t oidx = ((size_t)(layer * T_STEPS + t) * BATCH + bglob) * HID + aj;
            out[oidx]            = h_new;
            out[SECT + oidx]     = c_new;
            out[2 * SECT + oidx] = i_t;
            out[3 * SECT + oidx] = f_t;
            out[4 * SECT + oidx] = g_t;
            out[5 * SECT + oidx] = o_t;
        }

        // ---- group barrier: release-red + acquire-spin (64 arrivals) ----
        __syncthreads();
        if (tid == 0) {
            asm volatile("red.release.gpu.global.add.u32 [%0], 1;" :: "l"(bar) : "memory");
            const unsigned target = (unsigned)(t + 1) * GBLK;
            unsigned v;
            do {
                asm volatile("ld.acquire.gpu.global.u32 %0, [%1];" : "=r"(v) : "l"(bar) : "memory");
            } while (v < target);
        }
        __syncthreads();
    }
}

// ---------------- launch ----------------
extern "C" void kernel_launch(void* const* d_in, const int* in_sizes, int n_in,
                              void* d_out, int out_size)
{
    (void)in_sizes; (void)n_in; (void)out_size;
    const float* x    = (const float*)d_in[0];
    const float* w_ih = (const float*)d_in[1];
    const float* w_hh = (const float*)d_in[2];
    const float* b_ih = (const float*)d_in[3];
    const float* b_hh = (const float*)d_in[4];
    float* out = (float*)d_out;

    const int smem = (BPG * STRIDE + 512 * PSTR) * 4;  // 73984 B
    cudaFuncSetAttribute(lstm_layer, cudaFuncAttributeMaxDynamicSharedMemorySize, smem);

    dim3 gg(T_STEPS * BATCH / 128, G4 / 128);  // (128, 16)
    for (int l = 0; l < 2; l++) {
        const float* A = (l == 0) ? x : out;   // layer-1 input = layer-0 h
        pre_gemm_tc<<<gg, 256>>>(A, w_ih + (size_t)l * G4 * HID,
                                 b_ih + (size_t)l * G4, b_hh + (size_t)l * G4);
        reset_bar<<<1, 32>>>();
        lstm_layer<<<NBLK, 512, smem>>>(l, w_hh + (size_t)l * G4 * HID, out);
    }
}